// round 13
// baseline (speedup 1.0000x reference)
#include <cuda_runtime.h>
#include <cuda_fp16.h>
#include <math.h>

// Problem dims (fixed by reference setup_inputs)
#define BB 64
#define FF 128
#define TT 4096
#define KK 13
#define NN (BB*TT)   // 262144 samples per coefficient
#define T2 (TT/2)
#define K1_BLOCKS (8*64*2)

// ---- device scratch (static: no allocation allowed; zero-init at load) ----
// One 64-byte record per sample n: {cT[13] fp16, pad3, cP[13] fp16, pad3}
__device__ __half   g_c[(size_t)NN * 32];
__device__ double   g_sum[2][KK];
__device__ double   g_sumsq[2][KK];
__device__ float    g_fin[3][KK];      // srT, srP, soff (written by K1 last block)
__device__ double   g_mcd_acc;
__device__ unsigned g_k1count;
__device__ unsigned g_k2count;

// ---- packed fp32x2 helpers (Blackwell FFMA2 via PTX) ----
__device__ __forceinline__ unsigned long long pack2(float x, float y) {
    unsigned long long r;
    asm("mov.b64 %0, {%1, %2};" : "=l"(r) : "f"(x), "f"(y));
    return r;
}
__device__ __forceinline__ void unpack2(unsigned long long v, float& x, float& y) {
    asm("mov.b64 {%0, %1}, %2;" : "=f"(x), "=f"(y) : "l"(v));
}
__device__ __forceinline__ void fma2(unsigned long long& a,
                                     unsigned long long w,
                                     unsigned long long v) {
    asm("fma.rn.f32x2 %0, %1, %2, %0;" : "+l"(a) : "l"(w), "l"(v));
}

// pack 13 floats (+3 zero pad) into two uint4 as fp16
__device__ __forceinline__ void pack13(const float* v, uint4& u0, uint4& u1) {
    __half2* h0 = (__half2*)&u0;
    __half2* h1 = (__half2*)&u1;
    h0[0] = __floats2half2_rn(v[0],  v[1]);
    h0[1] = __floats2half2_rn(v[2],  v[3]);
    h0[2] = __floats2half2_rn(v[4],  v[5]);
    h0[3] = __floats2half2_rn(v[6],  v[7]);
    h1[0] = __floats2half2_rn(v[8],  v[9]);
    h1[1] = __floats2half2_rn(v[10], v[11]);
    h1[2] = __floats2half2_rn(v[12], 0.f);
    h1[3] = __floats2half2_rn(0.f,   0.f);
}

// ---------------------------------------------------------------------------
// K1: log2(1+|x|) -> folded 13-pt DCT (packed f32x2 FMAs), fp16 cepstra into
// interleaved 64B records, fused stats; LAST block finalizes mean/rstd to
// float constants (no FP64 left for K2).
// blockIdx.z selects tensor (0=true, 1=pred). Basis in smem as {w,w} pairs.
// Grid: (TT/512, BB, 2) x 256; each thread owns 2 adjacent t (float2).
// ---------------------------------------------------------------------------
__global__ __launch_bounds__(256) void k1_dct(const float* __restrict__ xt,
                                              const float* __restrict__ xp) {
    __shared__ float2 sb[KK][FF/2];     // {w, w} duplicated
    for (int i = threadIdx.x; i < KK * (FF/2); i += blockDim.x) {
        int k = i >> 6, f = i & 63;
        // sqrt(1/128), sqrt(2/128)=0.125 ; ln2 folded in (we use log2)
        float scale = (k == 0) ? 0.088388347648318447f : 0.125f;
        float w = cospif((float)((2*f + 1) * k) * (1.0f/256.0f))
                * scale * 0.69314718055994531f;
        sb[k][f] = make_float2(w, w);
    }
    __syncthreads();

    const int   b   = blockIdx.y;
    const int   z   = blockIdx.z;
    const float* src = z ? xp : xt;

    const int t2 = blockIdx.x * blockDim.x + threadIdx.x;   // float2 idx along T
    const float2* px = (const float2*)(src + (size_t)b * FF * TT) + t2;

    unsigned long long acc[KK];   // packed (ax, ay) fp32 pairs
#pragma unroll
    for (int k = 0; k < KK; k++) acc[k] = 0ull;

    const int PF = 4;
    float2 bl[PF], bh[PF];
#pragma unroll
    for (int j = 0; j < PF; j++) {
        bl[j] = __ldcs(px + (size_t)j * T2);
        bh[j] = __ldcs(px + (size_t)(FF-1-j) * T2);
    }

#pragma unroll 1
    for (int f0 = 0; f0 < FF/2; f0 += PF) {
        float2 cl[PF], ch[PF];
#pragma unroll
        for (int j = 0; j < PF; j++) { cl[j] = bl[j]; ch[j] = bh[j]; }
        if (f0 + PF < FF/2) {
#pragma unroll
            for (int j = 0; j < PF; j++) {
                bl[j] = __ldcs(px + (size_t)(f0 + PF + j) * T2);
                bh[j] = __ldcs(px + (size_t)(FF-1 - (f0 + PF + j)) * T2);
            }
        }
#pragma unroll
        for (int j = 0; j < PF; j++) {
            float llx = __log2f(1.0f + fabsf(cl[j].x));
            float lly = __log2f(1.0f + fabsf(cl[j].y));
            float lhx = __log2f(1.0f + fabsf(ch[j].x));
            float lhy = __log2f(1.0f + fabsf(ch[j].y));
            unsigned long long vs = pack2(llx + lhx, lly + lhy);
            unsigned long long vd = pack2(llx - lhx, lly - lhy);
            const unsigned long long* wrow =
                (const unsigned long long*)&sb[0][f0 + j];
#pragma unroll
            for (int k = 0; k < KK; k++) {
                // sb is [KK][64] float2 -> row stride 64 in ull units
                unsigned long long w = wrow[(size_t)k * (FF/2)];
                fma2(acc[k], w, (k & 1) ? vd : vs);
            }
        }
    }

    // unpack accumulators
    float ax[KK], ay[KK];
#pragma unroll
    for (int k = 0; k < KK; k++) unpack2(acc[k], ax[k], ay[k]);

    // interleaved store: record n is 4 uint4; this z owns uint4 slots {2z, 2z+1}
    const int n2 = b * T2 + t2;            // pair index; samples 2*n2, 2*n2+1
    uint4 u0, u1, u2, u3;
    pack13(ax, u0, u1);
    pack13(ay, u2, u3);
    uint4* base = (uint4*)g_c;
    base[(size_t)8 * n2     + 2*z    ] = u0;
    base[(size_t)8 * n2     + 2*z + 1] = u1;
    base[(size_t)8 * n2 + 4 + 2*z    ] = u2;
    base[(size_t)8 * n2 + 4 + 2*z + 1] = u3;

    // ---- fused stats: warp reduce -> shared -> one double atomic per k
    __shared__ float shS[KK], shQ[KK];
    if (threadIdx.x < KK) { shS[threadIdx.x] = 0.f; shQ[threadIdx.x] = 0.f; }
    __syncthreads();

    const int lane = threadIdx.x & 31;
#pragma unroll
    for (int k = 0; k < KK; k++) {
        float s = ax[k] + ay[k];
        float q = fmaf(ax[k], ax[k], ay[k] * ay[k]);
#pragma unroll
        for (int o = 16; o > 0; o >>= 1) {
            s += __shfl_down_sync(0xffffffffu, s, o);
            q += __shfl_down_sync(0xffffffffu, q, o);
        }
        if (lane == 0) { atomicAdd(&shS[k], s); atomicAdd(&shQ[k], q); }
    }
    __syncthreads();
    if (threadIdx.x < KK) {
        atomicAdd(&g_sum[z][threadIdx.x],   (double)shS[threadIdx.x]);
        atomicAdd(&g_sumsq[z][threadIdx.x], (double)shQ[threadIdx.x]);
    }
    __syncthreads();

    // ---- last block finalizes the normalization constants (once, double)
    if (threadIdx.x < 32) {
        unsigned done = 0;
        if (threadIdx.x == 0) {
            __threadfence();
            done = atomicAdd(&g_k1count, 1u);
        }
        done = __shfl_sync(0xffffffffu, done, 0);
        if (done == K1_BLOCKS - 1) {
            if (threadIdx.x < KK) {
                int k = threadIdx.x;
                double sT = atomicAdd(&g_sum[0][k], 0.0);
                double qT = atomicAdd(&g_sumsq[0][k], 0.0);
                double sP = atomicAdd(&g_sum[1][k], 0.0);
                double qP = atomicAdd(&g_sumsq[1][k], 0.0);
                double mT = sT / (double)NN;
                double vT = (qT - sT * sT / (double)NN) / (double)(NN - 1);
                if (vT < 0.0) vT = 0.0;
                double rT = 1.0 / (sqrt(vT) + 1e-6);
                double mP = sP / (double)NN;
                double vP = (qP - sP * sP / (double)NN) / (double)(NN - 1);
                if (vP < 0.0) vP = 0.0;
                double rP = 1.0 / (sqrt(vP) + 1e-6);
                g_fin[0][k] = (float)rT;
                g_fin[1][k] = (float)rP;
                g_fin[2][k] = (float)(mT * rT - mP * rP);
                // reset accumulators for the next graph replay
                g_sum[0][k] = 0.0; g_sum[1][k] = 0.0;
                g_sumsq[0][k] = 0.0; g_sumsq[1][k] = 0.0;
            }
            __syncwarp();
            if (threadIdx.x == 0) {
                __threadfence();
                g_k1count = 0u;
            }
        }
    }
}

// ---------------------------------------------------------------------------
// K2: mcd over all (b,t) from interleaved 64B records; preamble is 39 float
// loads (no FP64). Last block writes the scalar and resets state.
// Grid 1024 x 256 — one sample per thread, 4 contiguous LDG.128.
// ---------------------------------------------------------------------------
__global__ __launch_bounds__(256) void k2_mcd(float* __restrict__ out) {
    __shared__ float srT[KK], srP[KK], soff[KK];
    if (threadIdx.x < KK) {
        srT[threadIdx.x]  = g_fin[0][threadIdx.x];
        srP[threadIdx.x]  = g_fin[1][threadIdx.x];
        soff[threadIdx.x] = g_fin[2][threadIdx.x];
    }
    __syncthreads();

    const int n = blockIdx.x * blockDim.x + threadIdx.x;   // 0 .. NN-1 exact

    const uint4* rec = (const uint4*)g_c + (size_t)n * 4;
    uint4 a0 = rec[0], a1 = rec[1];     // cT[0..12]
    uint4 b0 = rec[2], b1 = rec[3];     // cP[0..12]

    float cT[14], cP[14];
    {
        const __half2* hT0 = (const __half2*)&a0;
        const __half2* hT1 = (const __half2*)&a1;
        const __half2* hP0 = (const __half2*)&b0;
        const __half2* hP1 = (const __half2*)&b1;
#pragma unroll
        for (int j = 0; j < 4; j++) {
            float2 t0 = __half22float2(hT0[j]);
            float2 p0 = __half22float2(hP0[j]);
            cT[2*j] = t0.x;   cT[2*j+1] = t0.y;
            cP[2*j] = p0.x;   cP[2*j+1] = p0.y;
        }
#pragma unroll
        for (int j = 0; j < 3; j++) {
            float2 t1 = __half22float2(hT1[j]);
            float2 p1 = __half22float2(hP1[j]);
            cT[8+2*j] = t1.x; cT[8+2*j+1] = t1.y;
            cP[8+2*j] = p1.x; cP[8+2*j+1] = p1.y;
        }
    }

    float s = 0.f;
#pragma unroll
    for (int k = 0; k < KK; k++) {
        float d = fmaf(cT[k], srT[k], -soff[k]) - cP[k] * srP[k];
        s = fmaf(d, d, s);
    }
    float acc = sqrtf(2.0f * s);

    __shared__ float sh_acc;
    if (threadIdx.x == 0) sh_acc = 0.f;
    __syncthreads();
#pragma unroll
    for (int o = 16; o > 0; o >>= 1) acc += __shfl_down_sync(0xffffffffu, acc, o);
    if ((threadIdx.x & 31) == 0) atomicAdd(&sh_acc, acc);
    __syncthreads();

    if (threadIdx.x == 0) {
        atomicAdd(&g_mcd_acc, (double)sh_acc);
        __threadfence();
        unsigned done = atomicAdd(&g_k2count, 1u);
        if (done == gridDim.x - 1) {
            double total = atomicAdd(&g_mcd_acc, 0.0);
            out[0] = (float)(total * 4.342944819032518 / (double)NN);  // 10/ln10, /N
            g_mcd_acc = 0.0;
            __threadfence();
            g_k2count = 0u;
        }
    }
}

extern "C" void kernel_launch(void* const* d_in, const int* in_sizes, int n_in,
                              void* d_out, int out_size) {
    const float* mel_true = (const float*)d_in[0];
    const float* mel_pred = (const float*)d_in[1];
    float* out = (float*)d_out;

    dim3 g1(TT / 512, BB, 2);        // 8 x 64 x 2 = 1024 blocks, 2 t per thread
    k1_dct<<<g1, 256>>>(mel_true, mel_pred);

    k2_mcd<<<1024, 256>>>(out);      // 1 sample per thread, exact cover
}

// round 14
// speedup vs baseline: 1.1108x; 1.1108x over previous
#include <cuda_runtime.h>
#include <cuda_fp16.h>
#include <math.h>

// Problem dims (fixed by reference setup_inputs)
#define BB 64
#define FF 128
#define TT 4096
#define KK 13
#define NN (BB*TT)     // 262144 samples per coefficient
#define T4 (TT/4)      // float4 units along T

#define GRID1 256      // persistent grid: must be <= co-resident capacity (296)
#define SPB   1024     // samples per block (4 per thread)

// ---- device scratch (static: no allocation allowed; zero-init at load) ----
__device__ double   g_sum[2][KK];
__device__ double   g_sumsq[2][KK];
__device__ double   g_mcd_acc;
__device__ unsigned g_arrive;
__device__ unsigned g_depart;

// ---- packed fp32x2 helpers (Blackwell FFMA2 via PTX) ----
__device__ __forceinline__ unsigned long long pack2(float x, float y) {
    unsigned long long r;
    asm("mov.b64 %0, {%1, %2};" : "=l"(r) : "f"(x), "f"(y));
    return r;
}
__device__ __forceinline__ void unpack2(unsigned long long v, float& x, float& y) {
    asm("mov.b64 {%0, %1}, %2;" : "=f"(x), "=f"(y) : "l"(v));
}
__device__ __forceinline__ void fma2(unsigned long long& a,
                                     unsigned long long w,
                                     unsigned long long v) {
    asm("fma.rn.f32x2 %0, %1, %2, %0;" : "+l"(a) : "l"(w), "l"(v));
}

// Dynamic smem layout:
//   [0, 6656)        float2 basis[KK][64]   ({w,w} pairs, ln2+scale folded)
//   [6656, 59904)    __half cep[2][KK][SPB] (per-block cepstra, both tensors)
#define SMEM_BASIS 0
#define SMEM_CEP   6656
#define SMEM_TOTAL 59904

// ---------------------------------------------------------------------------
// Persistent fused kernel:
//  phase 1: log2(1+|x|) -> folded 13-pt DCT (f32x2 FMAs) for both tensors,
//           cepstra -> SMEM (fp16), stats -> global double atomics
//  grid barrier (arrive counter + spin; grid sized to be fully co-resident)
//  phase 2: finalize mean/rstd per block, MCD from SMEM cepstra, last block
//           writes the scalar and resets all global state for graph replay.
// Block bx: b = bx>>2, t-chunk = bx&3. Thread owns 4 consecutive t (float4).
// ---------------------------------------------------------------------------
__global__ __launch_bounds__(256, 2) void mcd_fused(const float* __restrict__ xt,
                                                    const float* __restrict__ xp,
                                                    float* __restrict__ out) {
    extern __shared__ char dsm[];
    float2* sbasis = (float2*)(dsm + SMEM_BASIS);          // [KK][64]
    __half* cep    = (__half*)(dsm + SMEM_CEP);            // [2][KK][SPB]

    __shared__ float shS[2][KK], shQ[2][KK];
    __shared__ float srT[KK], srP[KK], soff[KK];
    __shared__ float sh_acc;

    const int tid = threadIdx.x;

    // build basis: {w,w} duplicated, dct scale and ln2 folded in
    for (int i = tid; i < KK * 64; i += blockDim.x) {
        int k = i >> 6, f = i & 63;
        float scale = (k == 0) ? 0.088388347648318447f : 0.125f;
        float w = cospif((float)((2*f + 1) * k) * (1.0f/256.0f))
                * scale * 0.69314718055994531f;
        sbasis[i] = make_float2(w, w);
    }
    if (tid < 2 * KK) {
        ((float*)shS)[tid] = 0.f;
        ((float*)shQ)[tid] = 0.f;
    }
    if (tid == 0) sh_acc = 0.f;
    __syncthreads();

    const int b  = blockIdx.x >> 2;
    const int tc = blockIdx.x & 3;
    const int t4 = tc * 256 + tid;          // float4 index along T
    const int lane = tid & 31;

    // ---------------- phase 1: DCT + stats, cepstra to smem ----------------
#pragma unroll 1
    for (int z = 0; z < 2; z++) {
        const float* src = z ? xp : xt;
        const float4* px = (const float4*)(src + (size_t)b * FF * TT) + t4;

        unsigned long long a01[KK], a23[KK];   // packed accum pairs (s0,s1),(s2,s3)
#pragma unroll
        for (int k = 0; k < KK; k++) { a01[k] = 0ull; a23[k] = 0ull; }

        const int PF = 4;
        float4 bl[PF], bh[PF];
#pragma unroll
        for (int j = 0; j < PF; j++) {
            bl[j] = __ldcs(px + (size_t)j * T4);
            bh[j] = __ldcs(px + (size_t)(FF-1-j) * T4);
        }

#pragma unroll 1
        for (int f0 = 0; f0 < 64; f0 += PF) {
            float4 cl[PF], ch[PF];
#pragma unroll
            for (int j = 0; j < PF; j++) { cl[j] = bl[j]; ch[j] = bh[j]; }
            if (f0 + PF < 64) {
#pragma unroll
                for (int j = 0; j < PF; j++) {
                    bl[j] = __ldcs(px + (size_t)(f0 + PF + j) * T4);
                    bh[j] = __ldcs(px + (size_t)(FF-1 - (f0 + PF + j)) * T4);
                }
            }
#pragma unroll
            for (int j = 0; j < PF; j++) {
                float l0 = __log2f(1.0f + fabsf(cl[j].x));
                float l1 = __log2f(1.0f + fabsf(cl[j].y));
                float l2 = __log2f(1.0f + fabsf(cl[j].z));
                float l3 = __log2f(1.0f + fabsf(cl[j].w));
                float h0 = __log2f(1.0f + fabsf(ch[j].x));
                float h1 = __log2f(1.0f + fabsf(ch[j].y));
                float h2 = __log2f(1.0f + fabsf(ch[j].z));
                float h3 = __log2f(1.0f + fabsf(ch[j].w));
                unsigned long long vs01 = pack2(l0 + h0, l1 + h1);
                unsigned long long vs23 = pack2(l2 + h2, l3 + h3);
                unsigned long long vd01 = pack2(l0 - h0, l1 - h1);
                unsigned long long vd23 = pack2(l2 - h2, l3 - h3);
                const unsigned long long* wrow =
                    (const unsigned long long*)&sbasis[f0 + j];
#pragma unroll
                for (int k = 0; k < KK; k++) {
                    unsigned long long w = wrow[(size_t)k * 64];
                    if (k & 1) { fma2(a01[k], w, vd01); fma2(a23[k], w, vd23); }
                    else       { fma2(a01[k], w, vs01); fma2(a23[k], w, vs23); }
                }
            }
        }

        // unpack, cepstra to smem (one STS.64 per k), stats reduce
#pragma unroll
        for (int k = 0; k < KK; k++) {
            float c0, c1, c2, c3;
            unpack2(a01[k], c0, c1);
            unpack2(a23[k], c2, c3);

            __half2 p0 = __floats2half2_rn(c0, c1);
            __half2 p1 = __floats2half2_rn(c2, c3);
            __half2* dstp = (__half2*)&cep[((size_t)z * KK + k) * SPB + tid * 4];
            dstp[0] = p0;
            dstp[1] = p1;

            float s = (c0 + c1) + (c2 + c3);
            float q = fmaf(c0, c0, c1 * c1) + fmaf(c2, c2, c3 * c3);
#pragma unroll
            for (int o = 16; o > 0; o >>= 1) {
                s += __shfl_down_sync(0xffffffffu, s, o);
                q += __shfl_down_sync(0xffffffffu, q, o);
            }
            if (lane == 0) { atomicAdd(&shS[z][k], s); atomicAdd(&shQ[z][k], q); }
        }
    }
    __syncthreads();

    if (tid < 2 * KK) {
        int z = tid / KK, k = tid % KK;
        atomicAdd(&g_sum[z][k],   (double)shS[z][k]);
        atomicAdd(&g_sumsq[z][k], (double)shQ[z][k]);
    }

    // ---------------- grid barrier (grid is fully co-resident) ----------------
    if (tid == 0) {
        __threadfence();
        atomicAdd(&g_arrive, 1u);
        while (*(volatile unsigned*)&g_arrive < GRID1) __nanosleep(64);
        __threadfence();
    }
    __syncthreads();

    // ---------------- finalize normalization (per block, double) --------------
    if (tid < KK) {
        int k = tid;
        double sT = g_sum[0][k], qT = g_sumsq[0][k];
        double sP = g_sum[1][k], qP = g_sumsq[1][k];
        double mT = sT / (double)NN;
        double vT = (qT - sT * sT / (double)NN) / (double)(NN - 1);
        if (vT < 0.0) vT = 0.0;
        double rT = 1.0 / (sqrt(vT) + 1e-6);
        double mP = sP / (double)NN;
        double vP = (qP - sP * sP / (double)NN) / (double)(NN - 1);
        if (vP < 0.0) vP = 0.0;
        double rP = 1.0 / (sqrt(vP) + 1e-6);
        srT[k]  = (float)rT;
        srP[k]  = (float)rP;
        soff[k] = (float)(mT * rT - mP * rP);
    }
    __syncthreads();

    // ---------------- phase 2: MCD from smem cepstra ---------------------------
    float s0 = 0.f, s1 = 0.f, s2 = 0.f, s3 = 0.f;
#pragma unroll
    for (int k = 0; k < KK; k++) {
        const __half2* pT = (const __half2*)&cep[((size_t)0 * KK + k) * SPB + tid * 4];
        const __half2* pP = (const __half2*)&cep[((size_t)1 * KK + k) * SPB + tid * 4];
        float2 t0 = __half22float2(pT[0]);
        float2 t1 = __half22float2(pT[1]);
        float2 p0 = __half22float2(pP[0]);
        float2 p1 = __half22float2(pP[1]);
        float rT = srT[k], rP = srP[k], of = soff[k];
        float d0 = fmaf(t0.x, rT, -of) - p0.x * rP;
        float d1 = fmaf(t0.y, rT, -of) - p0.y * rP;
        float d2 = fmaf(t1.x, rT, -of) - p1.x * rP;
        float d3 = fmaf(t1.y, rT, -of) - p1.y * rP;
        s0 = fmaf(d0, d0, s0);
        s1 = fmaf(d1, d1, s1);
        s2 = fmaf(d2, d2, s2);
        s3 = fmaf(d3, d3, s3);
    }
    float acc = (sqrtf(2.0f * s0) + sqrtf(2.0f * s1))
              + (sqrtf(2.0f * s2) + sqrtf(2.0f * s3));

#pragma unroll
    for (int o = 16; o > 0; o >>= 1) acc += __shfl_down_sync(0xffffffffu, acc, o);
    if (lane == 0) atomicAdd(&sh_acc, acc);
    __syncthreads();

    if (tid == 0) {
        atomicAdd(&g_mcd_acc, (double)sh_acc);
        __threadfence();
        unsigned done = atomicAdd(&g_depart, 1u);
        if (done == GRID1 - 1) {
            double total = atomicAdd(&g_mcd_acc, 0.0);
            out[0] = (float)(total * 4.342944819032518 / (double)NN);  // 10/ln10, /N
            // reset ALL persistent state for the next graph replay
            for (int k = 0; k < KK; k++) {
                g_sum[0][k] = 0.0; g_sum[1][k] = 0.0;
                g_sumsq[0][k] = 0.0; g_sumsq[1][k] = 0.0;
            }
            g_mcd_acc = 0.0;
            __threadfence();
            g_arrive = 0u;
            g_depart = 0u;
        }
    }
}

extern "C" void kernel_launch(void* const* d_in, const int* in_sizes, int n_in,
                              void* d_out, int out_size) {
    const float* mel_true = (const float*)d_in[0];
    const float* mel_pred = (const float*)d_in[1];
    float* out = (float*)d_out;

    static bool attr_set = false;
    if (!attr_set) {
        cudaFuncSetAttribute(mcd_fused,
                             cudaFuncAttributeMaxDynamicSharedMemorySize,
                             SMEM_TOTAL);
        attr_set = true;
    }

    mcd_fused<<<GRID1, 256, SMEM_TOTAL>>>(mel_true, mel_pred, out);
}